// round 16
// baseline (speedup 1.0000x reference)
#include <cuda_runtime.h>
#include <cuda_bf16.h>
#include <math.h>
#include <stdint.h>

// ---------------------------------------------------------------- constants
#define T_DIM 2048
#define B_DIM 16
#define D_DIM 1024
#define M_DIM (T_DIM * B_DIM)     // 32768
#define BD    (B_DIM * D_DIM)     // 16384
#define NSEG  16
#define SEGT  (T_DIM / NSEG)      // 128

// ---------------------------------------------------------------- scratch
__device__ float g_k[(size_t)M_DIM * D_DIM];              // sigmoid gate
__device__ float g_v[(size_t)M_DIM * D_DIM];              // tanh value
__device__ __nv_bfloat16 g_xh[(size_t)M_DIM * D_DIM];
__device__ __nv_bfloat16 g_xl[(size_t)M_DIM * D_DIM];
__device__ __nv_bfloat16 g_wkh[(size_t)D_DIM * D_DIM];
__device__ __nv_bfloat16 g_wkl[(size_t)D_DIM * D_DIM];
__device__ __nv_bfloat16 g_wvh[(size_t)D_DIM * D_DIM];
__device__ __nv_bfloat16 g_wvl[(size_t)D_DIM * D_DIM];
__device__ float g_segA[NSEG * BD];
__device__ float g_segB[NSEG * BD];
__device__ float g_hstart[NSEG * BD];

__device__ __forceinline__ float fast_sigmoid(float x) {
    return 1.0f / (1.0f + __expf(-x));
}
// tanh(z) = 2*sigmoid(2z) - 1 ; __expf-based, ~1e-6 abs err (<< 1e-3 budget)
__device__ __forceinline__ float fast_tanh(float x) {
    return 2.0f / (1.0f + __expf(-2.0f * x)) - 1.0f;
}

__device__ __forceinline__ uint32_t smem_u32(const void* p) {
    uint32_t a;
    asm("{ .reg .u64 t; cvta.to.shared.u64 t, %1; cvt.u32.u64 %0, t; }"
        : "=r"(a) : "l"(p));
    return a;
}

// ---------------------------------------------------------------- mbarrier
#define MBARRIER_INIT(addr, cnt) \
    asm volatile("mbarrier.init.shared.b64 [%0], %1;" :: "r"(addr), "r"(cnt) : "memory")

#define MBARRIER_ARRIVE(addr) \
    asm volatile("mbarrier.arrive.shared.b64 _, [%0];" :: "r"(addr) : "memory")

// arrive once this thread's prior cp.async complete. .noinc REQUIRED (R9 hang).
#define CP_ASYNC_MBAR_ARRIVE_NOINC(addr) \
    asm volatile("cp.async.mbarrier.arrive.noinc.shared::cta.b64 [%0];" :: "r"(addr) : "memory")

#define MBARRIER_WAIT_PARITY(mbar, parity) do {                                   \
    uint32_t _m = (mbar); uint32_t _p = (parity); uint32_t _done;                 \
    asm volatile("{\n\t.reg .pred p;\n\t"                                         \
        "mbarrier.try_wait.parity.acquire.cta.shared::cta.b64 p, [%1], %2;\n\t"   \
        "selp.b32 %0, 1, 0, p;\n\t}"                                              \
        : "=r"(_done) : "r"(_m), "r"(_p) : "memory");                             \
    if (!_done) {                                                                 \
        asm volatile("{\n\t.reg .pred P1;\n\t"                                    \
            "WL_%=:\n\t"                                                          \
            "mbarrier.try_wait.parity.acquire.cta.shared::cta.b64 P1, [%0], %1, 0x989680;\n\t" \
            "@P1 bra.uni WD_%=;\n\t"                                              \
            "bra.uni WL_%=;\n\t"                                                  \
            "WD_%=:\n\t}"                                                         \
            :: "r"(_m), "r"(_p) : "memory");                                      \
    }                                                                             \
} while (0)

// ---------------------------------------------------------------- fused split
// One launch for x, W_k, W_v. Linear float4 index space:
//   [0, n4x)            -> x    -> g_xh / g_xl
//   [n4x, n4x+n4w)      -> W_k  -> g_wkh / g_wkl
//   [n4x+n4w, n4x+2n4w) -> W_v  -> g_wvh / g_wvl
static constexpr int N4X = (M_DIM * D_DIM) / 4;      // 8388608
static constexpr int N4W = (D_DIM * D_DIM) / 4;      // 262144

__global__ __launch_bounds__(256)
void split_all_kernel(const float* __restrict__ x,
                      const float* __restrict__ Wk,
                      const float* __restrict__ Wv)
{
    int idx = blockIdx.x * 256 + threadIdx.x;
    const float* src;
    unsigned long long *hi, *lo;
    int i;
    if (idx < N4X) {
        src = x;  i = idx;
        hi = (unsigned long long*)g_xh; lo = (unsigned long long*)g_xl;
    } else if (idx < N4X + N4W) {
        src = Wk; i = idx - N4X;
        hi = (unsigned long long*)g_wkh; lo = (unsigned long long*)g_wkl;
    } else if (idx < N4X + 2 * N4W) {
        src = Wv; i = idx - N4X - N4W;
        hi = (unsigned long long*)g_wvh; lo = (unsigned long long*)g_wvl;
    } else {
        return;
    }
    float4 f = ((const float4*)src)[i];
    union { __nv_bfloat16 h[4]; unsigned long long u; } H, L;
    H.h[0] = __float2bfloat16(f.x);
    H.h[1] = __float2bfloat16(f.y);
    H.h[2] = __float2bfloat16(f.z);
    H.h[3] = __float2bfloat16(f.w);
    L.h[0] = __float2bfloat16(f.x - __bfloat162float(H.h[0]));
    L.h[1] = __float2bfloat16(f.y - __bfloat162float(H.h[1]));
    L.h[2] = __float2bfloat16(f.z - __bfloat162float(H.h[2]));
    L.h[3] = __float2bfloat16(f.w - __bfloat162float(H.h[3]));
    hi[i] = H.u;
    lo[i] = L.u;
}

// ---------------------------------------------------------------- fused GEMM
// R13 base (853 us, tensor 79.7%) + R16: split full barrier into A/W so
// consumers start A LDSMs before the producer's W loads have landed.
static constexpr int BM = 128, BN = 64, KCH = 32;
static constexpr int NCH = D_DIM / KCH;              // 32 chunks
static constexpr int ROWB = 2 * KCH * 2 + 16;        // 144 B
static constexpr int A_ST = BM * ROWB;               // 18432 B
static constexpr int W_ST = BN * ROWB;               // 9216 B
static constexpr int STAGE = A_ST + 2 * W_ST;        // 36864 B
static constexpr int NSTG = 3;
static constexpr int MBAR_OFF = NSTG * STAGE;
static constexpr int SMEM_SZ = MBAR_OFF + 128;       // 110720 B (x2 CTA fits)

#define CP_ASYNC16(dst, src) \
    asm volatile("cp.async.cg.shared.global [%0], [%1], 16;" :: "r"(dst), "l"(src))

#define LDSM_X4(r0, r1, r2, r3, addr) \
    asm volatile("ldmatrix.sync.aligned.m8n8.x4.shared.b16 {%0,%1,%2,%3}, [%4];" \
                 : "=r"(r0), "=r"(r1), "=r"(r2), "=r"(r3) : "r"(addr))

#define MMA_BF16(d, a, b) \
    asm volatile("mma.sync.aligned.m16n8k16.row.col.f32.bf16.bf16.f32 " \
                 "{%0,%1,%2,%3}, {%4,%5,%6,%7}, {%8,%9}, {%0,%1,%2,%3};" \
                 : "+f"((d)[0]), "+f"((d)[1]), "+f"((d)[2]), "+f"((d)[3]) \
                 : "r"((a)[0]), "r"((a)[1]), "r"((a)[2]), "r"((a)[3]),   \
                   "r"((b)[0]), "r"((b)[1]))

__global__ __launch_bounds__(288, 2)
void fused_gemm_kv(const float* __restrict__ bk, const float* __restrict__ bv)
{
    extern __shared__ char smem[];
    const uint32_t sb = smem_u32(smem);
    const int tid = threadIdx.x;
    const int wid = tid >> 5;          // 0..8
    const int lid = tid & 31;
    const int bm = blockIdx.y * BM;
    const int bn = blockIdx.x * BN;

    // fullA[0..2]: count 32 (producer lanes, noinc after A loads)
    // fullW[0..2]: count 32 (producer lanes, noinc after W loads)
    // empty[0..2]: count 8  (one arrive per consumer warp)
    const uint32_t mb_fullA = sb + MBAR_OFF;        // 3 x 8B
    const uint32_t mb_fullW = sb + MBAR_OFF + 24;   // 3 x 8B
    const uint32_t mb_empty = sb + MBAR_OFF + 48;   // 3 x 8B
    if (tid == 0) {
        #pragma unroll
        for (int s = 0; s < NSTG; ++s) {
            MBARRIER_INIT(mb_fullA + s * 8, 32);
            MBARRIER_INIT(mb_fullW + s * 8, 32);
            MBARRIER_INIT(mb_empty + s * 8, 8);
        }
    }
    __syncthreads();                                 // only CTA-wide sync

    if (wid == 8) {
        // ---------------- producer warp ----------------
        const int rA0 = lid >> 3;                    // 0..3
        const int cc  = lid & 7;                     // fixed 16B column
        const int gcol = (cc < 4 ? cc : cc - 4) * 8; // bf16 col in plane
        const bool hiP = (cc < 4);
        int st = 0, ph = 1;                          // first empty-waits pass
        for (int c = 0; c < NCH; ++c) {
            MBARRIER_WAIT_PARITY(mb_empty + st * 8, ph);
            const int kk = c * KCH;
            const uint32_t base = sb + st * STAGE;
            const __nv_bfloat16* Aplane = hiP ? g_xh : g_xl;
            #pragma unroll
            for (int j = 0; j < 32; ++j) {
                const int r = j * 4 + rA0;
                CP_ASYNC16(base + r * ROWB + cc * 16,
                           Aplane + (size_t)(bm + r) * D_DIM + kk + gcol);
            }
            CP_ASYNC_MBAR_ARRIVE_NOINC(mb_fullA + st * 8);  // covers A loads
            #pragma unroll
            for (int j = 0; j < 32; ++j) {
                const int rw = j * 4 + rA0;          // 0..127
                const int w = rw >> 6;               // 0 = Wk, 1 = Wv
                const int r = rw & 63;
                const __nv_bfloat16* Wplane = w
                    ? (hiP ? g_wvh : g_wvl)
                    : (hiP ? g_wkh : g_wkl);
                CP_ASYNC16(base + A_ST + w * W_ST + r * ROWB + cc * 16,
                           Wplane + (size_t)(bn + r) * D_DIM + kk + gcol);
            }
            CP_ASYNC_MBAR_ARRIVE_NOINC(mb_fullW + st * 8);  // covers A+W loads
            if (++st == NSTG) { st = 0; ph ^= 1; }
        }
        return;                                      // producer done
    }

    // ---------------- consumer warps (0..7) ----------------
    const int wm0 = (wid & 3) * 32;
    const int wn0 = (wid >> 2) * 32;

    float acc[2][2][4][4];
    #pragma unroll
    for (int o = 0; o < 2; ++o)
        #pragma unroll
        for (int i = 0; i < 2; ++i)
            #pragma unroll
            for (int j = 0; j < 4; ++j)
                #pragma unroll
                for (int r = 0; r < 4; ++r) acc[o][i][j][r] = 0.0f;

    const uint32_t a_row_off = (uint32_t)(wm0 + (lid & 15)) * ROWB + (lid >> 4) * 16;
    const uint32_t b_row_off = (uint32_t)(wn0 + (lid & 7) + ((lid >> 4) & 1) * 8) * ROWB
                             + ((lid >> 3) & 1) * 16;

    int st = 0, ph = 0;
    for (int c = 0; c < NCH; ++c) {
        const uint32_t Ab = sb + st * STAGE;

        uint32_t ah[2][4], al[2][4];
        uint32_t b[2][4][2];
        uint32_t bl2[2][4][2];       // s=1 lo-plane fragments (for early release)
        uint32_t ah1[2][4], al1[2][4];

        // A tile ready first: start A LDSMs before W has landed.
        MBARRIER_WAIT_PARITY(mb_fullA + st * 8, ph);
        {
            const uint32_t base0 = Ab + a_row_off;
            LDSM_X4(ah[0][0], ah[0][1], ah[0][2], ah[0][3], base0);
            LDSM_X4(al[0][0], al[0][1], al[0][2], al[0][3], base0 + 64);
            const uint32_t base1 = Ab + a_row_off + 16u * ROWB;
            LDSM_X4(ah[1][0], ah[1][1], ah[1][2], ah[1][3], base1);
            LDSM_X4(al[1][0], al[1][1], al[1][2], al[1][3], base1 + 64);
        }
        MBARRIER_WAIT_PARITY(mb_fullW + st * 8, ph);

        #pragma unroll
        for (int s = 0; s < 2; ++s) {
            uint32_t (*pah)[4] = (s == 0) ? ah : ah1;
            uint32_t (*pal)[4] = (s == 0) ? al : al1;
            if (s == 1) {
                #pragma unroll
                for (int mf = 0; mf < 2; ++mf) {
                    const uint32_t base = Ab + a_row_off + (uint32_t)mf * 16 * ROWB + 32;
                    LDSM_X4(pah[mf][0], pah[mf][1], pah[mf][2], pah[mf][3], base);
                    LDSM_X4(pal[mf][0], pal[mf][1], pal[mf][2], pal[mf][3], base + 64);
                }
            }
            // plane hi of W: Ah*Wh + Al*Wh
            #pragma unroll
            for (int o = 0; o < 2; ++o) {
                const uint32_t Bb = Ab + A_ST + o * W_ST;
                #pragma unroll
                for (int nf2 = 0; nf2 < 2; ++nf2) {
                    uint32_t addr = Bb + b_row_off + (uint32_t)nf2 * 16 * ROWB + s * 32;
                    LDSM_X4(b[o][nf2 * 2][0], b[o][nf2 * 2][1],
                            b[o][nf2 * 2 + 1][0], b[o][nf2 * 2 + 1][1], addr);
                }
            }
            #pragma unroll
            for (int o = 0; o < 2; ++o)
                #pragma unroll
                for (int mf = 0; mf < 2; ++mf)
                    #pragma unroll
                    for (int nf = 0; nf < 4; ++nf) {
                        MMA_BF16(acc[o][mf][nf], pah[mf], b[o][nf]);
                        MMA_BF16(acc[o][mf][nf], pal[mf], b[o][nf]);
                    }
            // plane lo of W
            if (s == 0) {
                #pragma unroll
                for (int o = 0; o < 2; ++o) {
                    const uint32_t Bb = Ab + A_ST + o * W_ST;
                    #pragma unroll
                    for (int nf2 = 0; nf2 < 2; ++nf2) {
                        uint32_t addr = Bb + b_row_off + (uint32_t)nf2 * 16 * ROWB + 64;
                        LDSM_X4(b[o][nf2 * 2][0], b[o][nf2 * 2][1],
                                b[o][nf2 * 2 + 1][0], b[o][nf2 * 2 + 1][1], addr);
                    }
                }
                #pragma unroll
                for (int o = 0; o < 2; ++o)
                    #pragma unroll
                    for (int mf = 0; mf < 2; ++mf)
                        #pragma unroll
                        for (int nf = 0; nf < 4; ++nf)
                            MMA_BF16(acc[o][mf][nf], pah[mf], b[o][nf]);
            } else {
                // s=1 lo-plane: LAST smem reads of this chunk -> load into
                // bl2, then release the stage BEFORE the trailing MMAs.
                #pragma unroll
                for (int o = 0; o < 2; ++o) {
                    const uint32_t Bb = Ab + A_ST + o * W_ST;
                    #pragma unroll
                    for (int nf2 = 0; nf2 < 2; ++nf2) {
                        uint32_t addr = Bb + b_row_off + (uint32_t)nf2 * 16 * ROWB
                                      + 32 + 64;
                        LDSM_X4(bl2[o][nf2 * 2][0], bl2[o][nf2 * 2][1],
                                bl2[o][nf2 * 2 + 1][0], bl2[o][nf2 * 2 + 1][1], addr);
                    }
                }
                __syncwarp();
                if (lid == 0) MBARRIER_ARRIVE(mb_empty + st * 8);  // EARLY release
                #pragma unroll
                for (int o = 0; o < 2; ++o)
                    #pragma unroll
                    for (int mf = 0; mf < 2; ++mf)
                        #pragma unroll
                        for (int nf = 0; nf < 4; ++nf)
                            MMA_BF16(acc[o][mf][nf], pah[mf], bl2[o][nf]);
            }
        }

        if (++st == NSTG) { st = 0; ph ^= 1; }
    }

    // epilogue: bias + activation, f32x2 stores (per-warp, no CTA sync)
    const int grow = lid >> 2;
    const int gcol = (lid & 3) * 2;
    #pragma unroll
    for (int o = 0; o < 2; ++o) {
        float* dst = o ? g_v : g_k;
        const float* bias = o ? bv : bk;
        #pragma unroll
        for (int nf = 0; nf < 4; ++nf) {
            const int col = bn + wn0 + nf * 8 + gcol;
            const float b0 = bias[col], b1 = bias[col + 1];
            #pragma unroll
            for (int mf = 0; mf < 2; ++mf) {
                const int r0 = bm + wm0 + mf * 16 + grow;
                float z0 = acc[o][mf][nf][0] + b0;
                float z1 = acc[o][mf][nf][1] + b1;
                float z2 = acc[o][mf][nf][2] + b0;
                float z3 = acc[o][mf][nf][3] + b1;
                float2 lo_, hi_;
                if (o == 0) {
                    lo_ = make_float2(fast_sigmoid(z0), fast_sigmoid(z1));
                    hi_ = make_float2(fast_sigmoid(z2), fast_sigmoid(z3));
                } else {
                    lo_ = make_float2(fast_tanh(z0), fast_tanh(z1));
                    hi_ = make_float2(fast_tanh(z2), fast_tanh(z3));
                }
                *(float2*)(dst + (size_t)r0 * D_DIM + col)       = lo_;
                *(float2*)(dst + (size_t)(r0 + 8) * D_DIM + col) = hi_;
            }
        }
    }
}

// ---------------------------------------------------------------- seg scan
// float2 vectorized — each thread owns 2 adjacent chains (i, i+1).
__global__ __launch_bounds__(256)
void scanA_kernel()
{
    const int p = blockIdx.x * 256 + threadIdx.x;     // 0..NSEG*BD/2-1
    const int i2 = p & (BD / 2 - 1);                  // chain pair
    const int s  = p >> 13;                           // BD/2 = 2^13
    const size_t base = (size_t)(s * SEGT) * BD + i2 * 2;

    const float2* __restrict__ kp = (const float2*)(g_k + base);
    const float2* __restrict__ vp = (const float2*)(g_v + base);
    const size_t str = BD / 2;                        // float2 stride per t

    float2 A = make_float2(1.0f, 1.0f), B = make_float2(0.0f, 0.0f);
    constexpr int U = 4;
    float2 ka[U], va[U], kb[U], vb[U];
    #pragma unroll
    for (int u = 0; u < U; ++u) { ka[u] = kp[u * str]; va[u] = vp[u * str]; }

    for (int j0 = 0; j0 < SEGT; j0 += U) {
        if (j0 + U < SEGT) {
            #pragma unroll
            for (int u = 0; u < U; ++u) {
                kb[u] = kp[(size_t)(j0 + U + u) * str];
                vb[u] = vp[(size_t)(j0 + U + u) * str];
            }
        }
        #pragma unroll
        for (int u = 0; u < U; ++u) {
            const float omx = 1.0f - ka[u].x, omy = 1.0f - ka[u].y;
            B.x = omx * B.x + ka[u].x * va[u].x;
            B.y = omy * B.y + ka[u].y * va[u].y;
            A.x = omx * A.x;
            A.y = omy * A.y;
        }
        #pragma unroll
        for (int u = 0; u < U; ++u) { ka[u] = kb[u]; va[u] = vb[u]; }
    }
    ((float2*)g_segA)[s * str + i2] = A;
    ((float2*)g_segB)[s * str + i2] = B;
}

__global__ __launch_bounds__(128)
void scanB_kernel(const float* __restrict__ h0, float* __restrict__ out_h)
{
    const int i = blockIdx.x * 128 + threadIdx.x;
    float h = h0[i];
    out_h[i] = h;
    #pragma unroll
    for (int s = 0; s < NSEG; ++s) {
        g_hstart[s * BD + i] = h;
        h = g_segA[s * BD + i] * h + g_segB[s * BD + i];
    }
}

__global__ __launch_bounds__(256)
void scanC_kernel(float* __restrict__ out_o, float* __restrict__ out_h)
{
    const int p = blockIdx.x * 256 + threadIdx.x;
    const int i2 = p & (BD / 2 - 1);
    const int s  = p >> 13;
    const size_t base = (size_t)(s * SEGT) * BD + i2 * 2;
    const size_t str = BD / 2;

    const float2* __restrict__ kp = (const float2*)(g_k + base);
    const float2* __restrict__ vp = (const float2*)(g_v + base);
    float2* __restrict__ op = (float2*)(out_o + base);
    float2* __restrict__ hp = (float2*)(out_h + BD + base);

    float2 h = ((const float2*)g_hstart)[s * str + i2];
    constexpr int U = 4;
    float2 ka[U], va[U], kb[U], vb[U];
    #pragma unroll
    for (int u = 0; u < U; ++u) { ka[u] = kp[u * str]; va[u] = vp[u * str]; }

    for (int j0 = 0; j0 < SEGT; j0 += U) {
        if (j0 + U < SEGT) {
            #pragma unroll
            for (int u = 0; u < U; ++u) {
                kb[u] = kp[(size_t)(j0 + U + u) * str];
                vb[u] = vp[(size_t)(j0 + U + u) * str];
            }
        }
        #pragma unroll
        for (int u = 0; u < U; ++u) {
            h.x = (1.0f - ka[u].x) * h.x + ka[u].x * va[u].x;
            h.y = (1.0f - ka[u].y) * h.y + ka[u].y * va[u].y;
            hp[(size_t)(j0 + u) * str] = h;
            float sx = fast_sigmoid(h.x);
            float sy = fast_sigmoid(h.y);
            op[(size_t)(j0 + u) * str] = make_float2(h.x * h.x * sx, h.y * h.y * sy);
        }
        #pragma unroll
        for (int u = 0; u < U; ++u) { ka[u] = kb[u]; va[u] = vb[u]; }
    }
}

// ---------------------------------------------------------------- launch
extern "C" void kernel_launch(void* const* d_in, const int* in_sizes, int n_in,
                              void* d_out, int out_size)
{
    const float* x   = (const float*)d_in[0];
    const float* h0  = (const float*)d_in[1];
    const float* W_k = (const float*)d_in[2];
    const float* b_k = (const float*)d_in[3];
    const float* W_v = (const float*)d_in[4];
    const float* b_v = (const float*)d_in[5];

    float* out   = (float*)d_out;
    float* out_o = out;                           // [T, B, D]
    float* out_h = out + (size_t)T_DIM * BD;      // [T+1, B, D]

    const int n4tot = N4X + 2 * N4W;              // 8912896
    split_all_kernel<<<(n4tot + 255) / 256, 256>>>(x, W_k, W_v);

    cudaFuncSetAttribute(fused_gemm_kv,
                         cudaFuncAttributeMaxDynamicSharedMemorySize, SMEM_SZ);
    dim3 grid(D_DIM / BN, M_DIM / BM);            // (16, 256)
    fused_gemm_kv<<<grid, 288, SMEM_SZ>>>(b_k, b_v);

    scanA_kernel<<<(NSEG * BD / 2) / 256, 256>>>();
    scanB_kernel<<<BD / 128, 128>>>(h0, out_h);
    scanC_kernel<<<(NSEG * BD / 2) / 256, 256>>>(out_o, out_h);
}

// round 17
// speedup vs baseline: 1.0141x; 1.0141x over previous
#include <cuda_runtime.h>
#include <cuda_bf16.h>
#include <math.h>
#include <stdint.h>

// ---------------------------------------------------------------- constants
#define T_DIM 2048
#define B_DIM 16
#define D_DIM 1024
#define M_DIM (T_DIM * B_DIM)     // 32768
#define BD    (B_DIM * D_DIM)     // 16384
#define NSEG  16
#define SEGT  (T_DIM / NSEG)      // 128

// ---------------------------------------------------------------- scratch
__device__ float g_k[(size_t)M_DIM * D_DIM];              // sigmoid gate
__device__ float g_v[(size_t)M_DIM * D_DIM];              // tanh value
__device__ __nv_bfloat16 g_xh[(size_t)M_DIM * D_DIM];
__device__ __nv_bfloat16 g_xl[(size_t)M_DIM * D_DIM];
__device__ __nv_bfloat16 g_wkh[(size_t)D_DIM * D_DIM];
__device__ __nv_bfloat16 g_wkl[(size_t)D_DIM * D_DIM];
__device__ __nv_bfloat16 g_wvh[(size_t)D_DIM * D_DIM];
__device__ __nv_bfloat16 g_wvl[(size_t)D_DIM * D_DIM];
__device__ float g_segA[NSEG * BD];
__device__ float g_segB[NSEG * BD];
__device__ float g_hstart[NSEG * BD];

__device__ __forceinline__ float fast_sigmoid(float x) {
    return 1.0f / (1.0f + __expf(-x));
}
// tanh(z) = 2*sigmoid(2z) - 1 ; __expf-based, ~1e-6 abs err (<< 1e-3 budget)
__device__ __forceinline__ float fast_tanh(float x) {
    return 2.0f / (1.0f + __expf(-2.0f * x)) - 1.0f;
}

__device__ __forceinline__ uint32_t smem_u32(const void* p) {
    uint32_t a;
    asm("{ .reg .u64 t; cvta.to.shared.u64 t, %1; cvt.u32.u64 %0, t; }"
        : "=r"(a) : "l"(p));
    return a;
}

// ---------------------------------------------------------------- mbarrier
#define MBARRIER_INIT(addr, cnt) \
    asm volatile("mbarrier.init.shared.b64 [%0], %1;" :: "r"(addr), "r"(cnt) : "memory")

#define MBARRIER_ARRIVE(addr) \
    asm volatile("mbarrier.arrive.shared.b64 _, [%0];" :: "r"(addr) : "memory")

// arrive once this thread's prior cp.async complete. .noinc REQUIRED (R9 hang).
#define CP_ASYNC_MBAR_ARRIVE_NOINC(addr) \
    asm volatile("cp.async.mbarrier.arrive.noinc.shared::cta.b64 [%0];" :: "r"(addr) : "memory")

#define MBARRIER_WAIT_PARITY(mbar, parity) do {                                   \
    uint32_t _m = (mbar); uint32_t _p = (parity); uint32_t _done;                 \
    asm volatile("{\n\t.reg .pred p;\n\t"                                         \
        "mbarrier.try_wait.parity.acquire.cta.shared::cta.b64 p, [%1], %2;\n\t"   \
        "selp.b32 %0, 1, 0, p;\n\t}"                                              \
        : "=r"(_done) : "r"(_m), "r"(_p) : "memory");                             \
    if (!_done) {                                                                 \
        asm volatile("{\n\t.reg .pred P1;\n\t"                                    \
            "WL_%=:\n\t"                                                          \
            "mbarrier.try_wait.parity.acquire.cta.shared::cta.b64 P1, [%0], %1, 0x989680;\n\t" \
            "@P1 bra.uni WD_%=;\n\t"                                              \
            "bra.uni WL_%=;\n\t"                                                  \
            "WD_%=:\n\t}"                                                         \
            :: "r"(_m), "r"(_p) : "memory");                                      \
    }                                                                             \
} while (0)

// ---------------------------------------------------------------- split
__global__ __launch_bounds__(256)
void split_kernel(const float* __restrict__ src,
                  __nv_bfloat16* __restrict__ hi,
                  __nv_bfloat16* __restrict__ lo, int n4)
{
    int i = blockIdx.x * 256 + threadIdx.x;
    if (i >= n4) return;
    float4 f = ((const float4*)src)[i];
    union { __nv_bfloat16 h[4]; unsigned long long u; } H, L;
    H.h[0] = __float2bfloat16(f.x);
    H.h[1] = __float2bfloat16(f.y);
    H.h[2] = __float2bfloat16(f.z);
    H.h[3] = __float2bfloat16(f.w);
    L.h[0] = __float2bfloat16(f.x - __bfloat162float(H.h[0]));
    L.h[1] = __float2bfloat16(f.y - __bfloat162float(H.h[1]));
    L.h[2] = __float2bfloat16(f.z - __bfloat162float(H.h[2]));
    L.h[3] = __float2bfloat16(f.w - __bfloat162float(H.h[3]));
    ((unsigned long long*)hi)[i] = H.u;
    ((unsigned long long*)lo)[i] = L.u;
}

// ---------------------------------------------------------------- fused GEMM
// R13/R15 config (best measured: 855 us, tensor 79.6%):
// Warp-specialized producer/consumer, 2 CTAs/SM, 288 threads:
//   warps 0-7: consumers (LDSM + MMA), 4(m) x 2(n), tile 128x64, both outputs
//   warp 8   : producer (all cp.async), mbarrier-paced
// EARLY stage release before the trailing MMA block (R12).
static constexpr int BM = 128, BN = 64, KCH = 32;
static constexpr int NCH = D_DIM / KCH;              // 32 chunks
static constexpr int ROWB = 2 * KCH * 2 + 16;        // 144 B
static constexpr int A_ST = BM * ROWB;               // 18432 B
static constexpr int W_ST = BN * ROWB;               // 9216 B
static constexpr int STAGE = A_ST + 2 * W_ST;        // 36864 B
static constexpr int NSTG = 3;
static constexpr int MBAR_OFF = NSTG * STAGE;
static constexpr int SMEM_SZ = MBAR_OFF + 64;        // 110656 B (x2 CTA fits)

#define CP_ASYNC16(dst, src) \
    asm volatile("cp.async.cg.shared.global [%0], [%1], 16;" :: "r"(dst), "l"(src))

#define LDSM_X4(r0, r1, r2, r3, addr) \
    asm volatile("ldmatrix.sync.aligned.m8n8.x4.shared.b16 {%0,%1,%2,%3}, [%4];" \
                 : "=r"(r0), "=r"(r1), "=r"(r2), "=r"(r3) : "r"(addr))

#define MMA_BF16(d, a, b) \
    asm volatile("mma.sync.aligned.m16n8k16.row.col.f32.bf16.bf16.f32 " \
                 "{%0,%1,%2,%3}, {%4,%5,%6,%7}, {%8,%9}, {%0,%1,%2,%3};" \
                 : "+f"((d)[0]), "+f"((d)[1]), "+f"((d)[2]), "+f"((d)[3]) \
                 : "r"((a)[0]), "r"((a)[1]), "r"((a)[2]), "r"((a)[3]),   \
                   "r"((b)[0]), "r"((b)[1]))

__global__ __launch_bounds__(288, 2)
void fused_gemm_kv(const float* __restrict__ bk, const float* __restrict__ bv)
{
    extern __shared__ char smem[];
    const uint32_t sb = smem_u32(smem);
    const int tid = threadIdx.x;
    const int wid = tid >> 5;          // 0..8
    const int lid = tid & 31;
    const int bm = blockIdx.y * BM;
    const int bn = blockIdx.x * BN;

    // full[0..2]: count 32 (producer lanes, noinc each)
    // empty[0..2]: count 8 (one arrive per consumer warp)
    const uint32_t mb_full  = sb + MBAR_OFF;        // 3 x 8B
    const uint32_t mb_empty = sb + MBAR_OFF + 24;   // 3 x 8B
    if (tid == 0) {
        #pragma unroll
        for (int s = 0; s < NSTG; ++s) {
            MBARRIER_INIT(mb_full  + s * 8, 32);
            MBARRIER_INIT(mb_empty + s * 8, 8);
        }
    }
    __syncthreads();                                 // only CTA-wide sync

    if (wid == 8) {
        // ---------------- producer warp ----------------
        const int rA0 = lid >> 3;                    // 0..3
        const int cc  = lid & 7;                     // fixed 16B column
        const int gcol = (cc < 4 ? cc : cc - 4) * 8; // bf16 col in plane
        const bool hiP = (cc < 4);
        int st = 0, ph = 1;                          // first empty-waits pass
        for (int c = 0; c < NCH; ++c) {
            MBARRIER_WAIT_PARITY(mb_empty + st * 8, ph);
            const int kk = c * KCH;
            const uint32_t base = sb + st * STAGE;
            const __nv_bfloat16* Aplane = hiP ? g_xh : g_xl;
            #pragma unroll
            for (int j = 0; j < 32; ++j) {
                const int r = j * 4 + rA0;
                CP_ASYNC16(base + r * ROWB + cc * 16,
                           Aplane + (size_t)(bm + r) * D_DIM + kk + gcol);
            }
            #pragma unroll
            for (int j = 0; j < 32; ++j) {
                const int rw = j * 4 + rA0;          // 0..127
                const int w = rw >> 6;               // 0 = Wk, 1 = Wv
                const int r = rw & 63;
                const __nv_bfloat16* Wplane = w
                    ? (hiP ? g_wvh : g_wvl)
                    : (hiP ? g_wkh : g_wkl);
                CP_ASYNC16(base + A_ST + w * W_ST + r * ROWB + cc * 16,
                           Wplane + (size_t)(bn + r) * D_DIM + kk + gcol);
            }
            CP_ASYNC_MBAR_ARRIVE_NOINC(mb_full + st * 8);
            if (++st == NSTG) { st = 0; ph ^= 1; }
        }
        return;                                      // producer done
    }

    // ---------------- consumer warps (0..7) ----------------
    const int wm0 = (wid & 3) * 32;
    const int wn0 = (wid >> 2) * 32;

    float acc[2][2][4][4];
    #pragma unroll
    for (int o = 0; o < 2; ++o)
        #pragma unroll
        for (int i = 0; i < 2; ++i)
            #pragma unroll
            for (int j = 0; j < 4; ++j)
                #pragma unroll
                for (int r = 0; r < 4; ++r) acc[o][i][j][r] = 0.0f;

    const uint32_t a_row_off = (uint32_t)(wm0 + (lid & 15)) * ROWB + (lid >> 4) * 16;
    const uint32_t b_row_off = (uint32_t)(wn0 + (lid & 7) + ((lid >> 4) & 1) * 8) * ROWB
                             + ((lid >> 3) & 1) * 16;

    int st = 0, ph = 0;
    for (int c = 0; c < NCH; ++c) {
        MBARRIER_WAIT_PARITY(mb_full + st * 8, ph);
        const uint32_t Ab = sb + st * STAGE;

        uint32_t ah[2][4], al[2][4];
        uint32_t b[2][4][2];
        uint32_t bl2[2][4][2];       // s=1 lo-plane fragments (for early release)
        uint32_t ah1[2][4], al1[2][4];

        #pragma unroll
        for (int s = 0; s < 2; ++s) {
            uint32_t (*pah)[4] = (s == 0) ? ah : ah1;
            uint32_t (*pal)[4] = (s == 0) ? al : al1;
            #pragma unroll
            for (int mf = 0; mf < 2; ++mf) {
                const uint32_t base = Ab + a_row_off + (uint32_t)mf * 16 * ROWB + s * 32;
                LDSM_X4(pah[mf][0], pah[mf][1], pah[mf][2], pah[mf][3], base);
                LDSM_X4(pal[mf][0], pal[mf][1], pal[mf][2], pal[mf][3], base + 64);
            }
            // plane hi of W: Ah*Wh + Al*Wh
            #pragma unroll
            for (int o = 0; o < 2; ++o) {
                const uint32_t Bb = Ab + A_ST + o * W_ST;
                #pragma unroll
                for (int nf2 = 0; nf2 < 2; ++nf2) {
                    uint32_t addr = Bb + b_row_off + (uint32_t)nf2 * 16 * ROWB + s * 32;
                    LDSM_X4(b[o][nf2 * 2][0], b[o][nf2 * 2][1],
                            b[o][nf2 * 2 + 1][0], b[o][nf2 * 2 + 1][1], addr);
                }
            }
            #pragma unroll
            for (int o = 0; o < 2; ++o)
                #pragma unroll
                for (int mf = 0; mf < 2; ++mf)
                    #pragma unroll
                    for (int nf = 0; nf < 4; ++nf) {
                        MMA_BF16(acc[o][mf][nf], pah[mf], b[o][nf]);
                        MMA_BF16(acc[o][mf][nf], pal[mf], b[o][nf]);
                    }
            // plane lo of W
            if (s == 0) {
                #pragma unroll
                for (int o = 0; o < 2; ++o) {
                    const uint32_t Bb = Ab + A_ST + o * W_ST;
                    #pragma unroll
                    for (int nf2 = 0; nf2 < 2; ++nf2) {
                        uint32_t addr = Bb + b_row_off + (uint32_t)nf2 * 16 * ROWB + 64;
                        LDSM_X4(b[o][nf2 * 2][0], b[o][nf2 * 2][1],
                                b[o][nf2 * 2 + 1][0], b[o][nf2 * 2 + 1][1], addr);
                    }
                }
                #pragma unroll
                for (int o = 0; o < 2; ++o)
                    #pragma unroll
                    for (int mf = 0; mf < 2; ++mf)
                        #pragma unroll
                        for (int nf = 0; nf < 4; ++nf)
                            MMA_BF16(acc[o][mf][nf], pah[mf], b[o][nf]);
            } else {
                // s=1 lo-plane: LAST smem reads of this chunk -> load into
                // bl2, then release the stage BEFORE the trailing MMAs.
                #pragma unroll
                for (int o = 0; o < 2; ++o) {
                    const uint32_t Bb = Ab + A_ST + o * W_ST;
                    #pragma unroll
                    for (int nf2 = 0; nf2 < 2; ++nf2) {
                        uint32_t addr = Bb + b_row_off + (uint32_t)nf2 * 16 * ROWB
                                      + 32 + 64;
                        LDSM_X4(bl2[o][nf2 * 2][0], bl2[o][nf2 * 2][1],
                                bl2[o][nf2 * 2 + 1][0], bl2[o][nf2 * 2 + 1][1], addr);
                    }
                }
                __syncwarp();
                if (lid == 0) MBARRIER_ARRIVE(mb_empty + st * 8);  // EARLY release
                #pragma unroll
                for (int o = 0; o < 2; ++o)
                    #pragma unroll
                    for (int mf = 0; mf < 2; ++mf)
                        #pragma unroll
                        for (int nf = 0; nf < 4; ++nf)
                            MMA_BF16(acc[o][mf][nf], pah[mf], bl2[o][nf]);
            }
        }

        if (++st == NSTG) { st = 0; ph ^= 1; }
    }

    // epilogue: bias + activation, f32x2 stores (per-warp, no CTA sync)
    const int grow = lid >> 2;
    const int gcol = (lid & 3) * 2;
    #pragma unroll
    for (int o = 0; o < 2; ++o) {
        float* dst = o ? g_v : g_k;
        const float* bias = o ? bv : bk;
        #pragma unroll
        for (int nf = 0; nf < 4; ++nf) {
            const int col = bn + wn0 + nf * 8 + gcol;
            const float b0 = bias[col], b1 = bias[col + 1];
            #pragma unroll
            for (int mf = 0; mf < 2; ++mf) {
                const int r0 = bm + wm0 + mf * 16 + grow;
                float z0 = acc[o][mf][nf][0] + b0;
                float z1 = acc[o][mf][nf][1] + b1;
                float z2 = acc[o][mf][nf][2] + b0;
                float z3 = acc[o][mf][nf][3] + b1;
                float2 lo_, hi_;
                if (o == 0) {
                    lo_ = make_float2(fast_sigmoid(z0), fast_sigmoid(z1));
                    hi_ = make_float2(fast_sigmoid(z2), fast_sigmoid(z3));
                } else {
                    lo_ = make_float2(fast_tanh(z0), fast_tanh(z1));
                    hi_ = make_float2(fast_tanh(z2), fast_tanh(z3));
                }
                *(float2*)(dst + (size_t)r0 * D_DIM + col)       = lo_;
                *(float2*)(dst + (size_t)(r0 + 8) * D_DIM + col) = hi_;
            }
        }
    }
}

// ---------------------------------------------------------------- seg scan
// float2 vectorized — each thread owns 2 adjacent chains (i, i+1).
__global__ __launch_bounds__(256)
void scanA_kernel()
{
    const int p = blockIdx.x * 256 + threadIdx.x;     // 0..NSEG*BD/2-1
    const int i2 = p & (BD / 2 - 1);                  // chain pair
    const int s  = p >> 13;                           // BD/2 = 2^13
    const size_t base = (size_t)(s * SEGT) * BD + i2 * 2;

    const float2* __restrict__ kp = (const float2*)(g_k + base);
    const float2* __restrict__ vp = (const float2*)(g_v + base);
    const size_t str = BD / 2;                        // float2 stride per t

    float2 A = make_float2(1.0f, 1.0f), B = make_float2(0.0f, 0.0f);
    constexpr int U = 4;
    float2 ka[U], va[U], kb[U], vb[U];
    #pragma unroll
    for (int u = 0; u < U; ++u) { ka[u] = kp[u * str]; va[u] = vp[u * str]; }

    for (int j0 = 0; j0 < SEGT; j0 += U) {
        if (j0 + U < SEGT) {
            #pragma unroll
            for (int u = 0; u < U; ++u) {
                kb[u] = kp[(size_t)(j0 + U + u) * str];
                vb[u] = vp[(size_t)(j0 + U + u) * str];
            }
        }
        #pragma unroll
        for (int u = 0; u < U; ++u) {
            const float omx = 1.0f - ka[u].x, omy = 1.0f - ka[u].y;
            B.x = omx * B.x + ka[u].x * va[u].x;
            B.y = omy * B.y + ka[u].y * va[u].y;
            A.x = omx * A.x;
            A.y = omy * A.y;
        }
        #pragma unroll
        for (int u = 0; u < U; ++u) { ka[u] = kb[u]; va[u] = vb[u]; }
    }
    ((float2*)g_segA)[s * str + i2] = A;
    ((float2*)g_segB)[s * str + i2] = B;
}

// Phase B: per chain-pair, prefix over NSEG segments. R17: prefetch ALL
// segment (A,B) pairs into registers first (independent loads -> one
// memory round-trip), then run the serial recurrence register-resident.
__global__ __launch_bounds__(128)
void scanB_kernel(const float* __restrict__ h0, float* __restrict__ out_h)
{
    const int p = blockIdx.x * 128 + threadIdx.x;     // 0..BD/2-1
    const size_t str = BD / 2;

    float2 A[NSEG], Bv[NSEG];
    #pragma unroll
    for (int s = 0; s < NSEG; ++s) {
        A[s]  = ((const float2*)g_segA)[s * str + p];
        Bv[s] = ((const float2*)g_segB)[s * str + p];
    }

    float2 h = ((const float2*)h0)[p];
    ((float2*)out_h)[p] = h;
    #pragma unroll
    for (int s = 0; s < NSEG; ++s) {
        ((float2*)g_hstart)[s * str + p] = h;
        h.x = A[s].x * h.x + Bv[s].x;
        h.y = A[s].y * h.y + Bv[s].y;
    }
}

__global__ __launch_bounds__(256)
void scanC_kernel(float* __restrict__ out_o, float* __restrict__ out_h)
{
    const int p = blockIdx.x * 256 + threadIdx.x;
    const int i2 = p & (BD / 2 - 1);
    const int s  = p >> 13;
    const size_t base = (size_t)(s * SEGT) * BD + i2 * 2;
    const size_t str = BD / 2;

    const float2* __restrict__ kp = (const float2*)(g_k + base);
    const float2* __restrict__ vp = (const float2*)(g_v + base);
    float2* __restrict__ op = (float2*)(out_o + base);
    float2* __restrict__ hp = (float2*)(out_h + BD + base);

    float2 h = ((const float2*)g_hstart)[s * str + i2];
    constexpr int U = 4;
    float2 ka[U], va[U], kb[U], vb[U];
    #pragma unroll
    for (int u = 0; u < U; ++u) { ka[u] = kp[u * str]; va[u] = vp[u * str]; }

    for (int j0 = 0; j0 < SEGT; j0 += U) {
        if (j0 + U < SEGT) {
            #pragma unroll
            for (int u = 0; u < U; ++u) {
                kb[u] = kp[(size_t)(j0 + U + u) * str];
                vb[u] = vp[(size_t)(j0 + U + u) * str];
            }
        }
        #pragma unroll
        for (int u = 0; u < U; ++u) {
            h.x = (1.0f - ka[u].x) * h.x + ka[u].x * va[u].x;
            h.y = (1.0f - ka[u].y) * h.y + ka[u].y * va[u].y;
            hp[(size_t)(j0 + u) * str] = h;
            float sx = fast_sigmoid(h.x);
            float sy = fast_sigmoid(h.y);
            op[(size_t)(j0 + u) * str] = make_float2(h.x * h.x * sx, h.y * h.y * sy);
        }
        #pragma unroll
        for (int u = 0; u < U; ++u) { ka[u] = kb[u]; va[u] = vb[u]; }
    }
}

// ---------------------------------------------------------------- launch
extern "C" void kernel_launch(void* const* d_in, const int* in_sizes, int n_in,
                              void* d_out, int out_size)
{
    const float* x   = (const float*)d_in[0];
    const float* h0  = (const float*)d_in[1];
    const float* W_k = (const float*)d_in[2];
    const float* b_k = (const float*)d_in[3];
    const float* W_v = (const float*)d_in[4];
    const float* b_v = (const float*)d_in[5];

    float* out   = (float*)d_out;
    float* out_o = out;                           // [T, B, D]
    float* out_h = out + (size_t)T_DIM * BD;      // [T+1, B, D]

    __nv_bfloat16 *xh, *xl, *wkh, *wkl, *wvh, *wvl;
    cudaGetSymbolAddress((void**)&xh,  g_xh);
    cudaGetSymbolAddress((void**)&xl,  g_xl);
    cudaGetSymbolAddress((void**)&wkh, g_wkh);
    cudaGetSymbolAddress((void**)&wkl, g_wkl);
    cudaGetSymbolAddress((void**)&wvh, g_wvh);
    cudaGetSymbolAddress((void**)&wvl, g_wvl);

    const int n4x = (M_DIM * D_DIM) / 4;
    const int n4w = (D_DIM * D_DIM) / 4;
    split_kernel<<<(n4x + 255) / 256, 256>>>(x,   xh,  xl,  n4x);
    split_kernel<<<(n4w + 255) / 256, 256>>>(W_k, wkh, wkl, n4w);
    split_kernel<<<(n4w + 255) / 256, 256>>>(W_v, wvh, wvl, n4w);

    cudaFuncSetAttribute(fused_gemm_kv,
                         cudaFuncAttributeMaxDynamicSharedMemorySize, SMEM_SZ);
    dim3 grid(D_DIM / BN, M_DIM / BM);            // (16, 256)
    fused_gemm_kv<<<grid, 288, SMEM_SZ>>>(b_k, b_v);

    scanA_kernel<<<(NSEG * BD / 2) / 256, 256>>>();
    scanB_kernel<<<(BD / 2) / 128, 128>>>(h0, out_h);
    scanC_kernel<<<(NSEG * BD / 2) / 256, 256>>>(out_o, out_h);
}